// round 11
// baseline (speedup 1.0000x reference)
#include <cuda_runtime.h>

#define NN 50000
#define NE 100000
#define NODE_IN 64
#define EDGE_IN 16
#define H 32
#define EH 128
#define NTN 343
#define NTE 21
#define STEPS 6
#define FULLM 0xffffffffu

#define CNT_BLKS ((NE + 1023) / 1024)             // 98
#define HT_BLKS ((NTN * H + 1023) / 1024)         // 11
#define SETUPA_BLKS (NTE + HT_BLKS + CNT_BLKS)
#define INIT_BLKS ((NN * H + 1023) / 1024)        // 1563

// ---------------- device scratch ----------------
__device__ float d_h[NN * H];
__device__ float d_agg[NN * H];
__device__ float d_Wtab[NTE * H * H];
__device__ float d_htab[NTN * H];
__device__ int d_ssrc[NE];
__device__ int d_sdst[NE];
__device__ int d_stype[NE];
__device__ int d_blkcnt[CNT_BLKS * NTE];

// ---------------- helpers ----------------
__device__ __forceinline__ unsigned long long pk(float a, float b) {
    unsigned long long r;
    asm("mov.b64 %0, {%1, %2};" : "=l"(r) : "f"(a), "f"(b));
    return r;
}
__device__ __forceinline__ float2 upk(unsigned long long v) {
    float2 f;
    asm("mov.b64 {%0, %1}, %2;" : "=f"(f.x), "=f"(f.y) : "l"(v));
    return f;
}
__device__ __forceinline__ void ffma2(unsigned long long& acc,
                                      unsigned long long a,
                                      unsigned long long b) {
    asm("fma.rn.f32x2 %0, %1, %2, %0;" : "+l"(acc) : "l"(a), "l"(b));
}
__device__ __forceinline__ float sigm(float x) {
    return 1.0f / (1.0f + __expf(-x));
}
__device__ __forceinline__ float tanh_fast(float x) {
    float e = __expf(2.0f * x);
    return 1.0f - 2.0f / (e + 1.0f);
}
__device__ __forceinline__ unsigned smem_u32(const void* p) {
    unsigned a;
    asm("{ .reg .u64 t; cvta.to.shared.u64 t, %1; cvt.u32.u64 %0, t; }"
        : "=r"(a) : "l"(p));
    return a;
}

// ---------------- launch 0: setup A (wtab | htab | count) ------------------
__global__ void __launch_bounds__(1024) k_setupA(
    const float* __restrict__ edge_emb, const float* __restrict__ eW1,
    const float* __restrict__ eb1, const float* __restrict__ eW2,
    const float* __restrict__ eb2, const float* __restrict__ node_emb,
    const float* __restrict__ proj_W, const float* __restrict__ proj_b,
    const int* __restrict__ eid) {
    int tid = threadIdx.x;
    int b = blockIdx.x;
    if (b < NTE) {
        __shared__ float sh[EH];
        if (tid < EH) {
            float a = eb1[tid];
#pragma unroll
            for (int i = 0; i < EDGE_IN; i++)
                a = fmaf(edge_emb[b * EDGE_IN + i], eW1[i * EH + tid], a);
            sh[tid] = fmaxf(a, 0.0f);
        }
        __syncthreads();
        float acc = eb2[tid];
#pragma unroll 8
        for (int i = 0; i < EH; i++)
            acc = fmaf(sh[i], eW2[i * (H * H) + tid], acc);
        d_Wtab[b * (H * H) + tid] = acc;
    } else if (b < NTE + HT_BLKS) {
        int idx = (b - NTE) * 1024 + tid;
        if (idx < NTN * H) {
            int r = idx >> 5, o = idx & 31;
            float acc = proj_b[o];
#pragma unroll 8
            for (int i = 0; i < NODE_IN; i++)
                acc = fmaf(node_emb[r * NODE_IN + i], proj_W[i * H + o], acc);
            d_htab[idx] = fmaxf(acc, 0.0f);
        }
    } else {
        __shared__ int hc[NTE];
        int cb2 = b - NTE - HT_BLKS;
        if (tid < NTE) hc[tid] = 0;
        __syncthreads();
        int e = cb2 * 1024 + tid;
        if (e < NE) atomicAdd(&hc[eid[e]], 1);
        __syncthreads();
        if (tid < NTE) d_blkcnt[cb2 * NTE + tid] = hc[tid];
    }
}

// ---------------- launch 1: scatter (blocks 0..97) | init gather (rest) ----
__global__ void __launch_bounds__(1024) k_scatter_init(
    const int* __restrict__ eid, const int* __restrict__ src,
    const int* __restrict__ dst, const int* __restrict__ node_ids) {
    int b = blockIdx.x;
    if (b < CNT_BLKS) {
        __shared__ int hc[NTE];
        __shared__ int hbase[NTE];
        __shared__ int htot[NTE];
        if (threadIdx.x < NTE) hc[threadIdx.x] = 0;
        __syncthreads();
        int e = b * 1024 + threadIdx.x;
        int t = 0, loc = 0;
        bool valid = (e < NE);
        if (valid) {
            t = eid[e];
            loc = atomicAdd(&hc[t], 1);
        }
        __syncthreads();
        if (threadIdx.x < NTE) {
            int tt = threadIdx.x, before = 0, total = 0;
            for (int bb = 0; bb < CNT_BLKS; bb++) {
                int c = d_blkcnt[bb * NTE + tt];
                total += c;
                if (bb < b) before += c;
            }
            hbase[tt] = before;
            htot[tt] = total;
        }
        __syncthreads();
        if (threadIdx.x == 0) {
            int run = 0;
            for (int tt = 0; tt < NTE; tt++) {
                hbase[tt] += run;
                run += htot[tt];
            }
        }
        __syncthreads();
        if (valid) {
            int p = hbase[t] + loc;
            d_ssrc[p] = src[e];
            d_sdst[p] = dst[e];
            d_stype[p] = t;
        }
    } else {
        int idx = (b - CNT_BLKS) * 1024 + threadIdx.x;
        if (idx < NN * H) {
            int n = idx >> 5, o = idx & 31;
            d_h[idx] = d_htab[node_ids[n] * H + o];
            d_agg[idx] = 0.0f;
        }
    }
}

// ---------------- launch 2 (even): message kernel --------------------------
// 128-thread blocks -> grid 782 (~5.3 blocks/SM) for deeper residency.
#define MSG_TPB 128
#define MSG_WPB (MSG_TPB / 32)
#define MSG_NCH (NE / 32)
#define MSG_BLOCKS ((MSG_NCH + MSG_WPB - 1) / MSG_WPB)  // 782

__global__ void __launch_bounds__(MSG_TPB) k_message() {
    __shared__ __align__(16) float hs[MSG_WPB][32][32];
    int wid = threadIdx.x >> 5;
    int lane = threadIdx.x & 31;
    int gw = blockIdx.x * MSG_WPB + wid;
    if (gw >= MSG_NCH) return;

    int e = gw * 32 + lane;
    int sI = __ldg(&d_ssrc[e]);
    int dI = __ldg(&d_sdst[e]);
    int tI = __ldg(&d_stype[e]);

    unsigned sbase = smem_u32(&hs[wid][0][lane]);
#pragma unroll
    for (int j = 0; j < 32; j++) {
        int sj = __shfl_sync(FULLM, sI, j);
        const float* gp = &d_h[sj * H + lane];
        asm volatile("cp.async.ca.shared.global [%0], [%1], 4;"
                     :: "r"(sbase + j * 32 * 4), "l"(gp));
    }
    asm volatile("cp.async.commit_group;");

    int cur_t = __shfl_sync(FULLM, tI, 0);
    unsigned long long w2[H / 2];
    {
        const float* Wt = d_Wtab + cur_t * (H * H);
#pragma unroll
        for (int q = 0; q < H / 2; q++)
            w2[q] = pk(Wt[(2 * q) * H + lane], Wt[(2 * q + 1) * H + lane]);
    }
    asm volatile("cp.async.wait_group 0;");
    __syncwarp();

#pragma unroll 2
    for (int j = 0; j < 32; j++) {
        int tj = __shfl_sync(FULLM, tI, j);
        if (tj != cur_t) {
            cur_t = tj;
            const float* Wt = d_Wtab + cur_t * (H * H);
#pragma unroll
            for (int q = 0; q < H / 2; q++)
                w2[q] = pk(Wt[(2 * q) * H + lane], Wt[(2 * q + 1) * H + lane]);
        }
        const ulonglong2* hp = (const ulonglong2*)hs[wid][j];
        unsigned long long acc = 0;
#pragma unroll
        for (int p = 0; p < 8; p++) {
            ulonglong2 hh = hp[p];
            ffma2(acc, hh.x, w2[2 * p]);
            ffma2(acc, hh.y, w2[2 * p + 1]);
        }
        float2 f = upk(acc);
        int dj = __shfl_sync(FULLM, dI, j);
        atomicAdd(&d_agg[dj * H + lane], f.x + f.y);
    }
}

// ---------------- launch 3 (PROFILED): GRU v4, 128-thread blocks -----------
// 2 threads/node split by GEMM side; 64 nodes/block, grid 782
// (~5.3 blocks/SM; launch_bounds(128,6) caps regs at 85 -> 6 blocks fit).
#define G4_TPB 128
#define G4_NPB (G4_TPB / 2)                        // 64 nodes/block
#define G4_BLOCKS ((NN + G4_NPB - 1) / G4_NPB)     // 782
#define WROW 68

__global__ void __launch_bounds__(G4_TPB, 6) k_gru4(
    const float* __restrict__ gWih, const float* __restrict__ gWhh,
    const float* __restrict__ gbih, const float* __restrict__ gbhh,
    const float* __restrict__ cb, float* __restrict__ outp) {
    __shared__ __align__(16) float sW[96 * WROW];  // row r: [Wih_r | pad | Whh_r]
    __shared__ float sb[192];
    __shared__ __align__(16) float scb[32];

    int tid = threadIdx.x;
    for (int i = tid; i < 96 * 32; i += G4_TPB) {
        int r = i >> 5, c = i & 31;
        sW[r * WROW + c] = __ldg(gWih + i);
        sW[r * WROW + 36 + c] = __ldg(gWhh + i);
    }
    if (tid < 96) {
        sb[tid] = __ldg(gbih + tid);
        sb[96 + tid] = __ldg(gbhh + tid);
    }
    if (tid < 32) scb[tid] = __ldg(cb + tid);
    __syncthreads();

    int nr = blockIdx.x * G4_NPB + (tid >> 1);
    int half = tid & 1;
    bool valid = (nr < NN);
    int n = valid ? nr : (NN - 1);  // clamp; stores predicated (keeps warp full for shfl)

    // hoist my side's input vector into 16 packed regs
    unsigned long long x2[16];
    if (half == 0) {
        float4* ap = (float4*)(d_agg + (size_t)n * H);
        const float4* cb4 = (const float4*)scb;
        float4 z4 = make_float4(0.f, 0.f, 0.f, 0.f);
#pragma unroll
        for (int p = 0; p < 8; p++) {
            float4 a = ap[p];
            float4 c = cb4[p];
            float m0 = fmaxf(a.x + c.x, 0.f);
            float m1 = fmaxf(a.y + c.y, 0.f);
            float m2v = fmaxf(a.z + c.z, 0.f);
            float m3 = fmaxf(a.w + c.w, 0.f);
            x2[2 * p] = pk(m0, m1);
            x2[2 * p + 1] = pk(m2v, m3);
            if (valid) ap[p] = z4;  // reset agg for next step
        }
    } else {
        const float4* hp = (const float4*)(d_h + (size_t)n * H);
#pragma unroll
        for (int p = 0; p < 8; p++) {
            float4 v = hp[p];
            x2[2 * p] = pk(v.x, v.y);
            x2[2 * p + 1] = pk(v.z, v.w);
        }
    }

    const float* wbase = sW + half * 36;
    const float* bbase = sb + half * 96;
    float* hrow = d_h + (size_t)n * H;
    float* orow = outp + (size_t)n * H;

#pragma unroll 4
    for (int oo = 0; oo < 16; oo++) {
        int o0 = 2 * oo, o1 = o0 + 1;
        const ulonglong2* R0 = (const ulonglong2*)(wbase + o0 * WROW);
        const ulonglong2* R1 = (const ulonglong2*)(wbase + o1 * WROW);
        const ulonglong2* Z0 = (const ulonglong2*)(wbase + (32 + o0) * WROW);
        const ulonglong2* Z1 = (const ulonglong2*)(wbase + (32 + o1) * WROW);
        const ulonglong2* N0 = (const ulonglong2*)(wbase + (64 + o0) * WROW);
        const ulonglong2* N1 = (const ulonglong2*)(wbase + (64 + o1) * WROW);
        unsigned long long ar0 = pk(bbase[o0], 0.f);
        unsigned long long ar1 = pk(bbase[o1], 0.f);
        unsigned long long az0 = pk(bbase[32 + o0], 0.f);
        unsigned long long az1 = pk(bbase[32 + o1], 0.f);
        unsigned long long an0 = pk(bbase[64 + o0], 0.f);
        unsigned long long an1 = pk(bbase[64 + o1], 0.f);
#pragma unroll
        for (int p = 0; p < 8; p++) {
            unsigned long long xa = x2[2 * p], xb = x2[2 * p + 1];
            ulonglong2 w;
            w = R0[p]; ffma2(ar0, xa, w.x); ffma2(ar0, xb, w.y);
            w = R1[p]; ffma2(ar1, xa, w.x); ffma2(ar1, xb, w.y);
            w = Z0[p]; ffma2(az0, xa, w.x); ffma2(az0, xb, w.y);
            w = Z1[p]; ffma2(az1, xa, w.x); ffma2(az1, xb, w.y);
            w = N0[p]; ffma2(an0, xa, w.x); ffma2(an0, xb, w.y);
            w = N1[p]; ffma2(an1, xa, w.x); ffma2(an1, xb, w.y);
        }
        float2 f;
        f = upk(ar0); float sr0 = f.x + f.y;
        f = upk(ar1); float sr1 = f.x + f.y;
        f = upk(az0); float sz0 = f.x + f.y;
        f = upk(az1); float sz1 = f.x + f.y;
        f = upk(an0); float sn0 = f.x + f.y;
        f = upk(an1); float sn1 = f.x + f.y;

        // cross the pair: lane finalizes o_self = o0 + half
        float er = __shfl_xor_sync(FULLM, half ? sr0 : sr1, 1);
        float ez = __shfl_xor_sync(FULLM, half ? sz0 : sz1, 1);
        float en = __shfl_xor_sync(FULLM, half ? sn0 : sn1, 1);
        float lr = half ? sr1 : sr0;
        float lz = half ? sz1 : sz0;
        float r = sigm(lr + er);
        float z = sigm(lz + ez);
        float i_n = half ? en : sn0;
        float h_n = half ? sn1 : en;
        float nv = tanh_fast(i_n + r * h_n);
        int o_self = o0 + half;
        float hold = hrow[o_self];  // L1 hit (read-before-own-write)
        float hnew = (1.0f - z) * nv + z * hold;
        if (valid) {
            hrow[o_self] = hnew;
            if (outp) orow[o_self] = hnew;
        }
    }
}

// ---------------- launch ----------------
extern "C" void kernel_launch(void* const* d_in, const int* in_sizes, int n_in,
                              void* d_out, int out_size) {
    const int* node_ids = (const int*)d_in[0];
    const int* edge_ids = (const int*)d_in[1];
    const int* src = (const int*)d_in[2];
    const int* dst = (const int*)d_in[3];
    const float* node_emb = (const float*)d_in[4];
    const float* edge_emb = (const float*)d_in[5];
    const float* proj_W = (const float*)d_in[6];
    const float* proj_b = (const float*)d_in[7];
    const float* eW1 = (const float*)d_in[8];
    const float* eb1 = (const float*)d_in[9];
    const float* eW2 = (const float*)d_in[10];
    const float* eb2 = (const float*)d_in[11];
    const float* conv_bias = (const float*)d_in[12];
    const float* gWih = (const float*)d_in[13];
    const float* gWhh = (const float*)d_in[14];
    const float* gbih = (const float*)d_in[15];
    const float* gbhh = (const float*)d_in[16];
    float* out = (float*)d_out;

    k_setupA<<<SETUPA_BLKS, 1024>>>(edge_emb, eW1, eb1, eW2, eb2,
                                    node_emb, proj_W, proj_b, edge_ids);   // 0
    k_scatter_init<<<CNT_BLKS + INIT_BLKS, 1024>>>(edge_ids, src, dst,
                                                   node_ids);              // 1

    for (int s = 0; s < STEPS; s++) {
        k_message<<<MSG_BLOCKS, MSG_TPB>>>();                              // 2, 4, ...
        float* op = (s == STEPS - 1) ? out : nullptr;
        k_gru4<<<G4_BLOCKS, G4_TPB>>>(gWih, gWhh, gbih, gbhh,              // 3 (profiled)
                                      conv_bias, op);
    }
}

// round 12
// speedup vs baseline: 1.2507x; 1.2507x over previous
#include <cuda_runtime.h>

#define NN 50000
#define NE 100000
#define NODE_IN 64
#define EDGE_IN 16
#define H 32
#define EH 128
#define NTN 343
#define NTE 21
#define STEPS 6
#define FULLM 0xffffffffu

#define CNT_BLKS ((NE + 1023) / 1024)             // 98
#define HT_BLKS ((NTN * H + 1023) / 1024)         // 11
#define TR_BLKS 3                                  // weight transpose (3072 entries)
#define SETUPA_BLKS (NTE + HT_BLKS + TR_BLKS + CNT_BLKS)
#define INIT_BLKS ((NN * H + 1023) / 1024)        // 1563

// ---------------- device scratch ----------------
__device__ float d_h[NN * H];
__device__ float d_agg[NN * H];
__device__ float d_Wtab[NTE * H * H];
__device__ float d_htab[NTN * H];
__device__ unsigned long long d_gwi[16 * 96];  // transposed+packed Wih
__device__ unsigned long long d_gwh[16 * 96];  // transposed+packed Whh
__device__ int d_ssrc[NE];
__device__ int d_sdst[NE];
__device__ int d_stype[NE];
__device__ int d_blkcnt[CNT_BLKS * NTE];

// ---------------- helpers ----------------
__device__ __forceinline__ unsigned long long pk(float a, float b) {
    unsigned long long r;
    asm("mov.b64 %0, {%1, %2};" : "=l"(r) : "f"(a), "f"(b));
    return r;
}
__device__ __forceinline__ float2 upk(unsigned long long v) {
    float2 f;
    asm("mov.b64 {%0, %1}, %2;" : "=f"(f.x), "=f"(f.y) : "l"(v));
    return f;
}
__device__ __forceinline__ void ffma2(unsigned long long& acc,
                                      unsigned long long a,
                                      unsigned long long b) {
    asm("fma.rn.f32x2 %0, %1, %2, %0;" : "+l"(acc) : "l"(a), "l"(b));
}
__device__ __forceinline__ float sigm(float x) {
    return 1.0f / (1.0f + __expf(-x));
}
__device__ __forceinline__ float tanh_fast(float x) {
    float e = __expf(2.0f * x);
    return 1.0f - 2.0f / (e + 1.0f);
}
__device__ __forceinline__ unsigned smem_u32(const void* p) {
    unsigned a;
    asm("{ .reg .u64 t; cvta.to.shared.u64 t, %1; cvt.u32.u64 %0, t; }"
        : "=r"(a) : "l"(p));
    return a;
}

// ---------------- launch 0: setup A (wtab | htab | transpose | count) ------
__global__ void __launch_bounds__(1024) k_setupA(
    const float* __restrict__ edge_emb, const float* __restrict__ eW1,
    const float* __restrict__ eb1, const float* __restrict__ eW2,
    const float* __restrict__ eb2, const float* __restrict__ node_emb,
    const float* __restrict__ proj_W, const float* __restrict__ proj_b,
    const int* __restrict__ eid, const float* __restrict__ gWih,
    const float* __restrict__ gWhh) {
    int tid = threadIdx.x;
    int b = blockIdx.x;
    if (b < NTE) {
        __shared__ float sh[EH];
        if (tid < EH) {
            float a = eb1[tid];
#pragma unroll
            for (int i = 0; i < EDGE_IN; i++)
                a = fmaf(edge_emb[b * EDGE_IN + i], eW1[i * EH + tid], a);
            sh[tid] = fmaxf(a, 0.0f);
        }
        __syncthreads();
        float acc = eb2[tid];
#pragma unroll 8
        for (int i = 0; i < EH; i++)
            acc = fmaf(sh[i], eW2[i * (H * H) + tid], acc);
        d_Wtab[b * (H * H) + tid] = acc;
    } else if (b < NTE + HT_BLKS) {
        int idx = (b - NTE) * 1024 + tid;
        if (idx < NTN * H) {
            int r = idx >> 5, o = idx & 31;
            float acc = proj_b[o];
#pragma unroll 8
            for (int i = 0; i < NODE_IN; i++)
                acc = fmaf(node_emb[r * NODE_IN + i], proj_W[i * H + o], acc);
            d_htab[idx] = fmaxf(acc, 0.0f);
        }
    } else if (b < NTE + HT_BLKS + TR_BLKS) {
        // transpose+pack GRU weights: d_gw*[q*96+row] = (W[row,2q], W[row,2q+1])
        int idx = (b - NTE - HT_BLKS) * 1024 + tid;
        if (idx < 2 * 16 * 96) {
            int side = idx / (16 * 96);
            int rem = idx - side * (16 * 96);
            int q = rem / 96, row = rem - q * 96;
            const float* W = side ? gWhh : gWih;
            unsigned long long v = pk(W[row * H + 2 * q], W[row * H + 2 * q + 1]);
            if (side) d_gwh[q * 96 + row] = v;
            else d_gwi[q * 96 + row] = v;
        }
    } else {
        __shared__ int hc[NTE];
        int cb2 = b - NTE - HT_BLKS - TR_BLKS;
        if (tid < NTE) hc[tid] = 0;
        __syncthreads();
        int e = cb2 * 1024 + tid;
        if (e < NE) atomicAdd(&hc[eid[e]], 1);
        __syncthreads();
        if (tid < NTE) d_blkcnt[cb2 * NTE + tid] = hc[tid];
    }
}

// ---------------- launch 1: scatter (blocks 0..97) | init gather (rest) ----
__global__ void __launch_bounds__(1024) k_scatter_init(
    const int* __restrict__ eid, const int* __restrict__ src,
    const int* __restrict__ dst, const int* __restrict__ node_ids) {
    int b = blockIdx.x;
    if (b < CNT_BLKS) {
        __shared__ int hc[NTE];
        __shared__ int hbase[NTE];
        __shared__ int htot[NTE];
        if (threadIdx.x < NTE) hc[threadIdx.x] = 0;
        __syncthreads();
        int e = b * 1024 + threadIdx.x;
        int t = 0, loc = 0;
        bool valid = (e < NE);
        if (valid) {
            t = eid[e];
            loc = atomicAdd(&hc[t], 1);
        }
        __syncthreads();
        if (threadIdx.x < NTE) {
            int tt = threadIdx.x, before = 0, total = 0;
            for (int bb = 0; bb < CNT_BLKS; bb++) {
                int c = d_blkcnt[bb * NTE + tt];
                total += c;
                if (bb < b) before += c;
            }
            hbase[tt] = before;
            htot[tt] = total;
        }
        __syncthreads();
        if (threadIdx.x == 0) {
            int run = 0;
            for (int tt = 0; tt < NTE; tt++) {
                hbase[tt] += run;
                run += htot[tt];
            }
        }
        __syncthreads();
        if (valid) {
            int p = hbase[t] + loc;
            d_ssrc[p] = src[e];
            d_sdst[p] = dst[e];
            d_stype[p] = t;
        }
    } else {
        int idx = (b - CNT_BLKS) * 1024 + threadIdx.x;
        if (idx < NN * H) {
            int n = idx >> 5, o = idx & 31;
            d_h[idx] = d_htab[node_ids[n] * H + o];
            d_agg[idx] = 0.0f;
        }
    }
}

// ---------------- launch 2 (even): message kernel --------------------------
#define MSG_TPB 256
#define MSG_WPB (MSG_TPB / 32)
#define MSG_NCH (NE / 32)
#define MSG_BLOCKS ((MSG_NCH + MSG_WPB - 1) / MSG_WPB)

__global__ void __launch_bounds__(MSG_TPB) k_message() {
    __shared__ __align__(16) float hs[MSG_WPB][32][32];
    int wid = threadIdx.x >> 5;
    int lane = threadIdx.x & 31;
    int gw = blockIdx.x * MSG_WPB + wid;
    if (gw >= MSG_NCH) return;

    int e = gw * 32 + lane;
    int sI = __ldg(&d_ssrc[e]);
    int dI = __ldg(&d_sdst[e]);
    int tI = __ldg(&d_stype[e]);

    unsigned sbase = smem_u32(&hs[wid][0][lane]);
#pragma unroll
    for (int j = 0; j < 32; j++) {
        int sj = __shfl_sync(FULLM, sI, j);
        const float* gp = &d_h[sj * H + lane];
        asm volatile("cp.async.ca.shared.global [%0], [%1], 4;"
                     :: "r"(sbase + j * 32 * 4), "l"(gp));
    }
    asm volatile("cp.async.commit_group;");

    int cur_t = __shfl_sync(FULLM, tI, 0);
    unsigned long long w2[H / 2];
    {
        const float* Wt = d_Wtab + cur_t * (H * H);
#pragma unroll
        for (int q = 0; q < H / 2; q++)
            w2[q] = pk(Wt[(2 * q) * H + lane], Wt[(2 * q + 1) * H + lane]);
    }
    asm volatile("cp.async.wait_group 0;");
    __syncwarp();

#pragma unroll 2
    for (int j = 0; j < 32; j++) {
        int tj = __shfl_sync(FULLM, tI, j);
        if (tj != cur_t) {
            cur_t = tj;
            const float* Wt = d_Wtab + cur_t * (H * H);
#pragma unroll
            for (int q = 0; q < H / 2; q++)
                w2[q] = pk(Wt[(2 * q) * H + lane], Wt[(2 * q + 1) * H + lane]);
        }
        const ulonglong2* hp = (const ulonglong2*)hs[wid][j];
        unsigned long long acc = 0;
#pragma unroll
        for (int p = 0; p < 8; p++) {
            ulonglong2 hh = hp[p];
            ffma2(acc, hh.x, w2[2 * p]);
            ffma2(acc, hh.y, w2[2 * p + 1]);
        }
        float2 f = upk(acc);
        int dj = __shfl_sync(FULLM, dI, j);
        atomicAdd(&d_agg[dj * H + lane], f.x + f.y);
    }
}

// ---------------- launch 3 (PROFILED): GRU v5 -------------------------------
// Weights in REGISTERS (48 packed f32x2 per thread from transposed table).
// lane = output column; warp side = (warp&1): even computes m@Wih gates,
// odd computes h@Whh gates, each over 8 nodes. Gate sums meet in smem;
// fused epilogue after one __syncthreads. 32 nodes/block, 256 threads.
#define G5_TPB 256
#define G5_NPB 32
#define G5_BLOCKS ((NN + G5_NPB - 1) / G5_NPB)  // 1563

__global__ void __launch_bounds__(G5_TPB, 2) k_gru5(
    const float* __restrict__ gbih, const float* __restrict__ gbhh,
    const float* __restrict__ cb, float* __restrict__ outp) {
    __shared__ __align__(16) float4 sm_m[G5_NPB * 8];
    __shared__ __align__(16) float4 sm_h[G5_NPB * 8];
    __shared__ __align__(16) float sgate[6][G5_NPB * 32];

    int tid = threadIdx.x;
    int warp = tid >> 5;
    int lane = tid & 31;
    int side = warp & 1;     // 0: input GEMM (m), 1: hidden GEMM (h)
    int n0 = (warp >> 1) * 8;
    int nbase = blockIdx.x * G5_NPB;

    // weight registers: 3 gates x 16 packed pairs, coalesced loads
    const unsigned long long* WT = side ? d_gwh : d_gwi;
    unsigned long long wr[16], wz[16], wn[16];
#pragma unroll
    for (int q = 0; q < 16; q++) {
        wr[q] = __ldg(&WT[q * 96 + lane]);
        wz[q] = __ldg(&WT[q * 96 + 32 + lane]);
        wn[q] = __ldg(&WT[q * 96 + 64 + lane]);
    }
    const float* bsrc = side ? gbhh : gbih;
    float b_r = __ldg(bsrc + lane);
    float b_z = __ldg(bsrc + 32 + lane);
    float b_n = __ldg(bsrc + 64 + lane);

    // stage m = relu(agg+cb) and h into smem; zero agg
    {
        int node = tid >> 3, p = tid & 7;
        int n = nbase + node;
        float4 mv = make_float4(0.f, 0.f, 0.f, 0.f);
        float4 hv = mv;
        if (n < NN) {
            float4 c = __ldg((const float4*)cb + p);
            float4* ap = (float4*)(d_agg + (size_t)n * H + 4 * p);
            float4 a = *ap;
            mv.x = fmaxf(a.x + c.x, 0.f);
            mv.y = fmaxf(a.y + c.y, 0.f);
            mv.z = fmaxf(a.z + c.z, 0.f);
            mv.w = fmaxf(a.w + c.w, 0.f);
            *ap = make_float4(0.f, 0.f, 0.f, 0.f);
            hv = *(const float4*)(d_h + (size_t)n * H + 4 * p);
        }
        sm_m[node * 8 + p] = mv;
        sm_h[node * 8 + p] = hv;
    }
    __syncthreads();

    // gemm: warp computes its side's 3 gates for its 8 nodes
    {
        const float4* vb = side ? sm_h : sm_m;
        float* sg_r = sgate[side * 3 + 0];
        float* sg_z = sgate[side * 3 + 1];
        float* sg_n = sgate[side * 3 + 2];
#pragma unroll 2
        for (int j = 0; j < 8; j++) {
            int node = n0 + j;
            const ulonglong2* vp = (const ulonglong2*)(vb + node * 8);
            unsigned long long ar = pk(b_r, 0.f);
            unsigned long long az = pk(b_z, 0.f);
            unsigned long long an = pk(b_n, 0.f);
#pragma unroll
            for (int p = 0; p < 8; p++) {
                ulonglong2 vv = vp[p];  // broadcast LDS.128
                ffma2(ar, vv.x, wr[2 * p]); ffma2(ar, vv.y, wr[2 * p + 1]);
                ffma2(az, vv.x, wz[2 * p]); ffma2(az, vv.y, wz[2 * p + 1]);
                ffma2(an, vv.x, wn[2 * p]); ffma2(an, vv.y, wn[2 * p + 1]);
            }
            float2 f;
            f = upk(ar); sg_r[node * 32 + lane] = f.x + f.y;
            f = upk(az); sg_z[node * 32 + lane] = f.x + f.y;
            f = upk(an); sg_n[node * 32 + lane] = f.x + f.y;
        }
    }
    __syncthreads();

    // epilogue: 4 outputs per thread, coalesced
    const float* smh = (const float*)sm_h;
#pragma unroll
    for (int k = 0; k < 4; k++) {
        int idx = k * G5_TPB + tid;      // node*32 + o
        int n = nbase + (idx >> 5);
        if (n < NN) {
            float ir = sgate[0][idx], iz = sgate[1][idx], in_ = sgate[2][idx];
            float hr = sgate[3][idx], hz = sgate[4][idx], hn = sgate[5][idx];
            float r = sigm(ir + hr);
            float z = sigm(iz + hz);
            float nv = tanh_fast(in_ + r * hn);
            float hold = smh[idx];
            float hnew = (1.0f - z) * nv + z * hold;
            size_t off = (size_t)nbase * H + idx;
            d_h[off] = hnew;
            if (outp) outp[off] = hnew;
        }
    }
}

// ---------------- launch ----------------
extern "C" void kernel_launch(void* const* d_in, const int* in_sizes, int n_in,
                              void* d_out, int out_size) {
    const int* node_ids = (const int*)d_in[0];
    const int* edge_ids = (const int*)d_in[1];
    const int* src = (const int*)d_in[2];
    const int* dst = (const int*)d_in[3];
    const float* node_emb = (const float*)d_in[4];
    const float* edge_emb = (const float*)d_in[5];
    const float* proj_W = (const float*)d_in[6];
    const float* proj_b = (const float*)d_in[7];
    const float* eW1 = (const float*)d_in[8];
    const float* eb1 = (const float*)d_in[9];
    const float* eW2 = (const float*)d_in[10];
    const float* eb2 = (const float*)d_in[11];
    const float* conv_bias = (const float*)d_in[12];
    const float* gWih = (const float*)d_in[13];
    const float* gWhh = (const float*)d_in[14];
    const float* gbih = (const float*)d_in[15];
    const float* gbhh = (const float*)d_in[16];
    float* out = (float*)d_out;

    k_setupA<<<SETUPA_BLKS, 1024>>>(edge_emb, eW1, eb1, eW2, eb2, node_emb,
                                    proj_W, proj_b, edge_ids, gWih, gWhh);  // 0
    k_scatter_init<<<CNT_BLKS + INIT_BLKS, 1024>>>(edge_ids, src, dst,
                                                   node_ids);               // 1

    for (int s = 0; s < STEPS; s++) {
        k_message<<<MSG_BLOCKS, MSG_TPB>>>();                               // 2, 4, ...
        float* op = (s == STEPS - 1) ? out : nullptr;
        k_gru5<<<G5_BLOCKS, G5_TPB>>>(gbih, gbhh, conv_bias, op);           // 3 (profiled)
    }
}